// round 8
// baseline (speedup 1.0000x reference)
#include <cuda_runtime.h>
#include <cuda_bf16.h>

#define DIMC   1024
#define BATCH  4
#define SEQL   2048
#define NHEADS 16
#define HDIM   64
#define NROWS  (BATCH*SEQL)   // 8192

typedef unsigned long long ull;

// ---- scratch: __device__ globals (no cudaMalloc anywhere) -------------------
__device__ __align__(16) float g_q[NROWS*DIMC];
__device__ __align__(16) float g_k[NROWS*DIMC];
__device__ __align__(16) float g_v[NROWS*DIMC];
__device__ __align__(16) float g_attn[NROWS*DIMC];

// ---- packed f32x2 helpers (FFMA2: 2x fp32 FMA per instruction) --------------
__device__ __forceinline__ ull pk2(float lo, float hi) {
    ull r; asm("mov.b64 %0, {%1,%2};" : "=l"(r) : "f"(lo), "f"(hi)); return r;
}
__device__ __forceinline__ void upk2(ull v, float& lo, float& hi) {
    asm("mov.b64 {%0,%1}, %2;" : "=f"(lo), "=f"(hi) : "l"(v));
}
__device__ __forceinline__ void ffma2(ull& c, ull a, ull b) {
    asm("fma.rn.f32x2 %0, %1, %2, %0;" : "+l"(c) : "l"(a), "l"(b));
}
__device__ __forceinline__ void fmul2(ull& c, ull a) {
    asm("mul.rn.f32x2 %0, %0, %1;" : "+l"(c) : "l"(a));
}

// ============================================================================
// GEMM: C[r,o] = sum_k A[r,k]*W[o,k] + bias[o]   (A:[R,1024], W:[1024,1024])
// 128x128x16 tiles, 256 threads, 8x8/thread (f32x2), register prefetch.
// asel: 0 -> external A, 1 -> g_attn.  csel: 0/1/2 -> g_q/g_k/g_v, 3 -> Cext.
// ============================================================================
#define BM   128
#define BN   128
#define BKG  16
#define SPAD 132

__global__ __launch_bounds__(256, 2)
void gemm_bias_k(const float* __restrict__ Aext, const float* __restrict__ W,
                 const float* __restrict__ bias, float* __restrict__ Cext,
                 int asel, int csel)
{
    __shared__ __align__(16) float As[BKG*SPAD];
    __shared__ __align__(16) float Bs[BKG*SPAD];

    const float* A = (asel == 1) ? (const float*)g_attn : Aext;
    float* C = (csel == 0) ? (float*)g_q : (csel == 1) ? (float*)g_k
             : (csel == 2) ? (float*)g_v : Cext;

    const int bm = blockIdx.y * BM;
    const int bn = blockIdx.x * BN;
    const int tid = threadIdx.x;
    const int tr = tid >> 4;      // 0..15 -> rows tr*8..+7
    const int tc = tid & 15;      // 0..15 -> cols {tc*4..+3} and {64+tc*4..+3}
    const int lrow = tid >> 2;    // 0..63
    const int lkq  = tid & 3;     // float4 within 16-wide k slab

    ull acc[8][4];
    #pragma unroll
    for (int i = 0; i < 8; i++) { acc[i][0]=0; acc[i][1]=0; acc[i][2]=0; acc[i][3]=0; }

    float4 a0r, a1r, w0r, w1r;
    {
        const float* ap = A + (size_t)(bm + lrow) * DIMC + lkq * 4;
        a0r = *(const float4*)ap;
        a1r = *(const float4*)(ap + (size_t)64 * DIMC);
        const float* wp = W + (size_t)(bn + lrow) * DIMC + lkq * 4;
        w0r = *(const float4*)wp;
        w1r = *(const float4*)(wp + (size_t)64 * DIMC);
    }

    for (int k0 = 0; k0 < DIMC; k0 += BKG) {
        {   // transpose-store the prefetched tile
            int r0 = lrow, r1 = lrow + 64, kb = lkq * 4;
            As[(kb+0)*SPAD+r0]=a0r.x; As[(kb+1)*SPAD+r0]=a0r.y;
            As[(kb+2)*SPAD+r0]=a0r.z; As[(kb+3)*SPAD+r0]=a0r.w;
            As[(kb+0)*SPAD+r1]=a1r.x; As[(kb+1)*SPAD+r1]=a1r.y;
            As[(kb+2)*SPAD+r1]=a1r.z; As[(kb+3)*SPAD+r1]=a1r.w;
            Bs[(kb+0)*SPAD+r0]=w0r.x; Bs[(kb+1)*SPAD+r0]=w0r.y;
            Bs[(kb+2)*SPAD+r0]=w0r.z; Bs[(kb+3)*SPAD+r0]=w0r.w;
            Bs[(kb+0)*SPAD+r1]=w1r.x; Bs[(kb+1)*SPAD+r1]=w1r.y;
            Bs[(kb+2)*SPAD+r1]=w1r.z; Bs[(kb+3)*SPAD+r1]=w1r.w;
        }
        __syncthreads();

        if (k0 + BKG < DIMC) {  // prefetch next tile
            const float* ap = A + (size_t)(bm + lrow) * DIMC + (k0 + BKG) + lkq * 4;
            a0r = *(const float4*)ap;
            a1r = *(const float4*)(ap + (size_t)64 * DIMC);
            const float* wp = W + (size_t)(bn + lrow) * DIMC + (k0 + BKG) + lkq * 4;
            w0r = *(const float4*)wp;
            w1r = *(const float4*)(wp + (size_t)64 * DIMC);
        }

        #pragma unroll
        for (int kk = 0; kk < BKG; kk++) {
            const float* as = &As[kk*SPAD + tr*8];
            float4 fa0 = *(const float4*)as;
            float4 fa1 = *(const float4*)(as + 4);
            const float* bs = &Bs[kk*SPAD + tc*4];
            float4 fb0 = *(const float4*)bs;
            float4 fb1 = *(const float4*)(bs + 64);
            ull rb0 = pk2(fb0.x, fb0.y), rb1 = pk2(fb0.z, fb0.w);
            ull rb2 = pk2(fb1.x, fb1.y), rb3 = pk2(fb1.z, fb1.w);
            float ra[8] = {fa0.x,fa0.y,fa0.z,fa0.w,fa1.x,fa1.y,fa1.z,fa1.w};
            #pragma unroll
            for (int i = 0; i < 8; i++) {
                ull a2 = pk2(ra[i], ra[i]);
                ffma2(acc[i][0], a2, rb0);
                ffma2(acc[i][1], a2, rb1);
                ffma2(acc[i][2], a2, rb2);
                ffma2(acc[i][3], a2, rb3);
            }
        }
        __syncthreads();
    }

    const int c0 = bn + tc * 4, c1 = c0 + 64;
    float4 bb0 = *(const float4*)(bias + c0);
    float4 bb1 = *(const float4*)(bias + c1);
    #pragma unroll
    for (int i = 0; i < 8; i++) {
        int r = bm + tr * 8 + i;
        float x0,x1,x2,x3;
        upk2(acc[i][0],x0,x1); upk2(acc[i][1],x2,x3);
        *(float4*)(C + (size_t)r*DIMC + c0) =
            make_float4(x0+bb0.x, x1+bb0.y, x2+bb0.z, x3+bb0.w);
        upk2(acc[i][2],x0,x1); upk2(acc[i][3],x2,x3);
        *(float4*)(C + (size_t)r*DIMC + c1) =
            make_float4(x0+bb1.x, x1+bb1.y, x2+bb1.z, x3+bb1.w);
    }
}

// ============================================================================
// Flash attention per (b, h, 64-query tile); streams keys in 64-wide tiles.
// Q/K stored d-major with XOR swizzle: element (d,r) at [d*64 + (r^(d&60))]
// -> LDS.128 reads at stride 64 are conflict-free, zero padding.
// Smem = 3 * 16KB = 49152 B exactly. P overlays K; online softmax via shfl.
// ============================================================================
__global__ __launch_bounds__(256)
void attn_k()
{
    __shared__ __align__(16) float Qt[64*64];
    __shared__ __align__(16) float KtPs[64*64];
    __shared__ __align__(16) float Vs[64*64];

    const int b  = blockIdx.z;
    const int h  = blockIdx.y;
    const int q0 = blockIdx.x * 64;
    const int tid = threadIdx.x;
    const int tr = tid >> 4;   // query-row group: rows tr*4..+3
    const int tc = tid & 15;   // key-col (S phase) / d-col (PV phase) group

    const float scale = 0.125f;   // HEAD_DIM^-0.5
    const float* Qg = g_q + (size_t)(b*SEQL + q0)*DIMC + h*HDIM;
    const float* Kg = g_k + (size_t)(b*SEQL)*DIMC + h*HDIM;
    const float* Vg = g_v + (size_t)(b*SEQL)*DIMC + h*HDIM;

    // load Q transposed (d-major, swizzled)
    #pragma unroll
    for (int l = 0; l < 4; l++) {
        int idx = tid + l*256;
        int row = idx >> 4, dq = idx & 15;
        float4 qv = *(const float4*)(Qg + (size_t)row*DIMC + dq*4);
        int sw = row ^ (dq*4);
        Qt[(dq*4+0)*64+sw]=qv.x; Qt[(dq*4+1)*64+sw]=qv.y;
        Qt[(dq*4+2)*64+sw]=qv.z; Qt[(dq*4+3)*64+sw]=qv.w;
    }

    float m_run[4], l_run[4];
    ull oacc[4][2];
    #pragma unroll
    for (int i = 0; i < 4; i++) {
        m_run[i] = -1e30f; l_run[i] = 0.f; oacc[i][0] = 0; oacc[i][1] = 0;
    }

    for (int t0 = 0; t0 < SEQL; t0 += 64) {
        __syncthreads();   // prev PV reads done (and Qt stores visible, 1st iter)
        #pragma unroll
        for (int l = 0; l < 4; l++) {   // K transposed+swizzled, V natural
            int idx = tid + l*256;
            int row = idx >> 4, dq = idx & 15;
            float4 kv = *(const float4*)(Kg + (size_t)(t0+row)*DIMC + dq*4);
            int sw = row ^ (dq*4);
            KtPs[(dq*4+0)*64+sw]=kv.x; KtPs[(dq*4+1)*64+sw]=kv.y;
            KtPs[(dq*4+2)*64+sw]=kv.z; KtPs[(dq*4+3)*64+sw]=kv.w;
            float4 vv = *(const float4*)(Vg + (size_t)(t0+row)*DIMC + dq*4);
            *(float4*)&Vs[row*64 + dq*4] = vv;
        }
        __syncthreads();

        // ---- S = Q K^T (4x4 per thread) ----
        ull sacc[4][2];
        #pragma unroll
        for (int i = 0; i < 4; i++) { sacc[i][0]=0; sacc[i][1]=0; }
        #pragma unroll 4
        for (int d = 0; d < 64; d++) {
            int swz = d & 60;
            float4 qv = *(const float4*)&Qt  [d*64 + ((tr*4) ^ swz)];
            float4 kv = *(const float4*)&KtPs[d*64 + ((tc*4) ^ swz)];
            ull k01 = pk2(kv.x, kv.y), k23 = pk2(kv.z, kv.w);
            float qa[4] = {qv.x, qv.y, qv.z, qv.w};
            #pragma unroll
            for (int i = 0; i < 4; i++) {
                ull q2 = pk2(qa[i], qa[i]);
                ffma2(sacc[i][0], q2, k01);
                ffma2(sacc[i][1], q2, k23);
            }
        }
        __syncthreads();   // all S reads of KtPs done before P overlay

        // ---- online softmax (per query row, reduce over 16-lane tc group) ----
        float p[4][4];
        #pragma unroll
        for (int i = 0; i < 4; i++) {
            float s0,s1,s2,s3;
            upk2(sacc[i][0],s0,s1); upk2(sacc[i][1],s2,s3);
            s0*=scale; s1*=scale; s2*=scale; s3*=scale;
            float mloc = fmaxf(fmaxf(s0,s1), fmaxf(s2,s3));
            #pragma unroll
            for (int sft = 1; sft < 16; sft <<= 1)
                mloc = fmaxf(mloc, __shfl_xor_sync(0xffffffffu, mloc, sft, 16));
            float m_new = fmaxf(m_run[i], mloc);
            float alpha = __expf(m_run[i] - m_new);
            p[i][0]=__expf(s0-m_new); p[i][1]=__expf(s1-m_new);
            p[i][2]=__expf(s2-m_new); p[i][3]=__expf(s3-m_new);
            float lloc = p[i][0]+p[i][1]+p[i][2]+p[i][3];
            #pragma unroll
            for (int sft = 1; sft < 16; sft <<= 1)
                lloc += __shfl_xor_sync(0xffffffffu, lloc, sft, 16);
            l_run[i] = l_run[i]*alpha + lloc;
            m_run[i] = m_new;
            ull a2 = pk2(alpha, alpha);
            fmul2(oacc[i][0], a2);
            fmul2(oacc[i][1], a2);
            // store P row (row-major overlay on KtPs)
            *(float4*)&KtPs[(tr*4+i)*64 + tc*4] =
                make_float4(p[i][0], p[i][1], p[i][2], p[i][3]);
        }
        __syncthreads();   // P visible

        // ---- O += P V (rows tr*4..+3, d-cols tc*4..+3) ----
        #pragma unroll 2
        for (int kc = 0; kc < 64; kc += 4) {
            float4 v0 = *(const float4*)&Vs[(kc+0)*64 + tc*4];
            float4 v1 = *(const float4*)&Vs[(kc+1)*64 + tc*4];
            float4 v2 = *(const float4*)&Vs[(kc+2)*64 + tc*4];
            float4 v3 = *(const float4*)&Vs[(kc+3)*64 + tc*4];
            ull v0a=pk2(v0.x,v0.y), v0b=pk2(v0.z,v0.w);
            ull v1a=pk2(v1.x,v1.y), v1b=pk2(v1.z,v1.w);
            ull v2a=pk2(v2.x,v2.y), v2b=pk2(v2.z,v2.w);
            ull v3a=pk2(v3.x,v3.y), v3b=pk2(v3.z,v3.w);
            #pragma unroll
            for (int i = 0; i < 4; i++) {
                float4 pv = *(const float4*)&KtPs[(tr*4+i)*64 + kc];
                ull p0=pk2(pv.x,pv.x), p1=pk2(pv.y,pv.y);
                ull p2=pk2(pv.z,pv.z), p3=pk2(pv.w,pv.w);
                ffma2(oacc[i][0], p0, v0a); ffma2(oacc[i][1], p0, v0b);
                ffma2(oacc[i][0], p1, v1a); ffma2(oacc[i][1], p1, v1b);
                ffma2(oacc[i][0], p2, v2a); ffma2(oacc[i][1], p2, v2b);
                ffma2(oacc[i][0], p3, v3a); ffma2(oacc[i][1], p3, v3b);
            }
        }
    }

    // ---- normalize + write [B,N,H*D] layout into g_attn ----
    #pragma unroll
    for (int i = 0; i < 4; i++) {
        float inv = 1.0f / l_run[i];
        float x0,x1,x2,x3;
        upk2(oacc[i][0],x0,x1); upk2(oacc[i][1],x2,x3);
        size_t off = (size_t)(b*SEQL + q0 + tr*4 + i)*DIMC + h*HDIM + tc*4;
        *(float4*)(g_attn + off) = make_float4(x0*inv, x1*inv, x2*inv, x3*inv);
    }
}

extern "C" void kernel_launch(void* const* d_in, const int* in_sizes, int n_in,
                              void* d_out, int out_size)
{
    const float* x   = (const float*)d_in[0];
    const float* ctx = (const float*)d_in[1];
    const float* Wq  = (const float*)d_in[2];
    const float* bq  = (const float*)d_in[3];
    const float* Wk  = (const float*)d_in[4];
    const float* bk  = (const float*)d_in[5];
    const float* Wv  = (const float*)d_in[6];
    const float* bv  = (const float*)d_in[7];
    const float* Wo  = (const float*)d_in[8];
    const float* bo  = (const float*)d_in[9];
    float* out = (float*)d_out;

    dim3 gg(DIMC / BN, NROWS / BM);        // (8, 64)
    gemm_bias_k<<<gg, 256>>>(x,   Wq, bq, nullptr, 0, 0);   // Q
    gemm_bias_k<<<gg, 256>>>(ctx, Wk, bk, nullptr, 0, 1);   // K
    gemm_bias_k<<<gg, 256>>>(ctx, Wv, bv, nullptr, 0, 2);   // V
    attn_k<<<dim3(SEQL/64, NHEADS, BATCH), 256>>>();        // flash attention
    gemm_bias_k<<<gg, 256>>>(nullptr, Wo, bo, out, 1, 3);   // O projection
}

// round 9
// speedup vs baseline: 1.2202x; 1.2202x over previous
#include <cuda_runtime.h>
#include <cuda_bf16.h>
#include <cstdint>

#define DIMC   1024
#define BATCH  4
#define SEQL   2048
#define NHEADS 16
#define HDIM   64
#define NROWS  (BATCH*SEQL)   // 8192

typedef unsigned long long ull;

// ---- scratch: __device__ globals (no cudaMalloc anywhere) -------------------
__device__ __align__(16) float g_q[NROWS*DIMC];
__device__ __align__(16) float g_k[NROWS*DIMC];
__device__ __align__(16) float g_v[NROWS*DIMC];
__device__ __align__(16) float g_attn[NROWS*DIMC];

// ---- packed f32x2 helpers (FFMA2) ------------------------------------------
__device__ __forceinline__ ull pk2(float lo, float hi) {
    ull r; asm("mov.b64 %0, {%1,%2};" : "=l"(r) : "f"(lo), "f"(hi)); return r;
}
__device__ __forceinline__ void upk2(ull v, float& lo, float& hi) {
    asm("mov.b64 {%0,%1}, %2;" : "=f"(lo), "=f"(hi) : "l"(v));
}
__device__ __forceinline__ void ffma2(ull& c, ull a, ull b) {
    asm("fma.rn.f32x2 %0, %1, %2, %0;" : "+l"(c) : "l"(a), "l"(b));
}
__device__ __forceinline__ void fmul2(ull& c, ull a) {
    asm("mul.rn.f32x2 %0, %0, %1;" : "+l"(c) : "l"(a));
}

// ============================================================================
// Tensor-core GEMM with bf16x3 split (near-fp32 accuracy):
//   C[r,o] = sum_k A[r,k]*W[o,k] + bias[o]
//   a = ah + al (bf16 each); C ~= Ah*Wh + Al*Wh + Ah*Wl  (lo*lo dropped, ~2^-16)
// Tiles 128x128x32, 512 threads (16 warps, 4x4), warp tile 32x32 via
// mma.sync.m16n8k16.bf16. Split happens at load time (fp32 LDG -> 2 bf16 STS).
// asel: 0 -> Aext, 1 -> g_attn.  csel: 0/1/2 -> g_q/g_k/g_v, 3 -> Cext.
// ============================================================================
#define TBM 128
#define TBN 128
#define TBK 32

// swizzled element index: row pitch 32 bf16 (64B, 4x 16B chunks)
// chunk' = chunk ^ ((row>>1)&3) -> ldmatrix over 8 consecutive rows is
// conflict-free (even rows hit 4 distinct low groups, odd rows 4 high groups).
__device__ __forceinline__ int swz(int row, int k) {
    return row * TBK + ((((k >> 3) ^ (row >> 1)) & 3) << 3) + (k & 7);
}

__device__ __forceinline__ void ldmx4(uint32_t* r, const __nv_bfloat16* p) {
    uint32_t a = (uint32_t)__cvta_generic_to_shared(p);
    asm volatile("ldmatrix.sync.aligned.m8n8.x4.shared.b16 {%0,%1,%2,%3}, [%4];"
        : "=r"(r[0]), "=r"(r[1]), "=r"(r[2]), "=r"(r[3]) : "r"(a));
}

__device__ __forceinline__ void mma16816(float* c, const uint32_t* a,
                                         uint32_t b0, uint32_t b1) {
    asm volatile(
        "mma.sync.aligned.m16n8k16.row.col.f32.bf16.bf16.f32 "
        "{%0,%1,%2,%3}, {%4,%5,%6,%7}, {%8,%9}, {%0,%1,%2,%3};"
        : "+f"(c[0]), "+f"(c[1]), "+f"(c[2]), "+f"(c[3])
        : "r"(a[0]), "r"(a[1]), "r"(a[2]), "r"(a[3]), "r"(b0), "r"(b1));
}

// split float4 -> 4 bf16 hi + 4 bf16 lo, packed as 8-byte words
__device__ __forceinline__ void split4(float4 v, ull& hi, ull& lo) {
    union { __nv_bfloat16 b[4]; ull u; } H, L;
    float x[4] = {v.x, v.y, v.z, v.w};
    #pragma unroll
    for (int i = 0; i < 4; i++) {
        __nv_bfloat16 h = __float2bfloat16(x[i]);
        H.b[i] = h;
        L.b[i] = __float2bfloat16(x[i] - __bfloat162float(h));
    }
    hi = H.u; lo = L.u;
}

__global__ __launch_bounds__(512, 1)
void gemm_tc(const float* __restrict__ Aext, const float* __restrict__ W,
             const float* __restrict__ bias, float* __restrict__ Cext,
             int asel, int csel)
{
    __shared__ __align__(16) __nv_bfloat16 sAh[TBM*TBK];
    __shared__ __align__(16) __nv_bfloat16 sAl[TBM*TBK];
    __shared__ __align__(16) __nv_bfloat16 sWh[TBN*TBK];
    __shared__ __align__(16) __nv_bfloat16 sWl[TBN*TBK];

    const float* A = (asel == 1) ? (const float*)g_attn : Aext;
    float* C = (csel == 0) ? (float*)g_q : (csel == 1) ? (float*)g_k
             : (csel == 2) ? (float*)g_v : Cext;

    const int bm = blockIdx.y * TBM;
    const int bn = blockIdx.x * TBN;
    const int tid  = threadIdx.x;
    const int wid  = tid >> 5;
    const int lane = tid & 31;
    const int m0 = (wid >> 2) * 32;     // warp tile origin
    const int n0 = (wid & 3) * 32;

    // loader mapping: thread covers (row, row+64) x one float4 (kq*4..+3)
    const int lrow = tid >> 3;          // 0..63
    const int lkq  = tid & 7;           // 0..7

    float acc[2][4][4];
    #pragma unroll
    for (int a = 0; a < 2; a++)
        #pragma unroll
        for (int b = 0; b < 4; b++)
            #pragma unroll
            for (int c = 0; c < 4; c++) acc[a][b][c] = 0.f;

    // prefetch first k-slab into registers
    float4 aP0, aP1, wP0, wP1;
    {
        const float* Ap = A + (size_t)(bm + lrow) * DIMC + lkq * 4;
        const float* Wp = W + (size_t)(bn + lrow) * DIMC + lkq * 4;
        aP0 = *(const float4*)Ap;  aP1 = *(const float4*)(Ap + (size_t)64*DIMC);
        wP0 = *(const float4*)Wp;  wP1 = *(const float4*)(Wp + (size_t)64*DIMC);
    }

    // ldmatrix per-lane address components (fixed per thread)
    const int ar  = lane & 15;                     // A row within 16
    const int akh = (lane >> 4) * 8;               // A k-half
    const int br  = (lane & 7) + ((lane >> 4) << 3); // B (W) row within 16
    const int bkh = ((lane >> 3) & 1) * 8;         // B k-half

    for (int k0 = 0; k0 < DIMC; k0 += TBK) {
        {   // split + store the prefetched slab
            ull h, l;
            split4(aP0, h, l);
            *(ull*)&sAh[swz(lrow,      lkq*4)] = h;
            *(ull*)&sAl[swz(lrow,      lkq*4)] = l;
            split4(aP1, h, l);
            *(ull*)&sAh[swz(lrow + 64, lkq*4)] = h;
            *(ull*)&sAl[swz(lrow + 64, lkq*4)] = l;
            split4(wP0, h, l);
            *(ull*)&sWh[swz(lrow,      lkq*4)] = h;
            *(ull*)&sWl[swz(lrow,      lkq*4)] = l;
            split4(wP1, h, l);
            *(ull*)&sWh[swz(lrow + 64, lkq*4)] = h;
            *(ull*)&sWl[swz(lrow + 64, lkq*4)] = l;
        }
        __syncthreads();

        if (k0 + TBK < DIMC) {  // prefetch next slab (overlaps mma)
            const float* Ap = A + (size_t)(bm + lrow) * DIMC + (k0 + TBK) + lkq * 4;
            const float* Wp = W + (size_t)(bn + lrow) * DIMC + (k0 + TBK) + lkq * 4;
            aP0 = *(const float4*)Ap;  aP1 = *(const float4*)(Ap + (size_t)64*DIMC);
            wP0 = *(const float4*)Wp;  wP1 = *(const float4*)(Wp + (size_t)64*DIMC);
        }

        #pragma unroll
        for (int kk = 0; kk < 2; kk++) {
            const int kb = kk * 16;
            uint32_t Ah[2][4], Al[2][4], Bh[2][4], Bl[2][4];
            #pragma unroll
            for (int mt = 0; mt < 2; mt++) {
                ldmx4(Ah[mt], &sAh[swz(m0 + mt*16 + ar, kb + akh)]);
                ldmx4(Al[mt], &sAl[swz(m0 + mt*16 + ar, kb + akh)]);
            }
            #pragma unroll
            for (int np = 0; np < 2; np++) {
                ldmx4(Bh[np], &sWh[swz(n0 + np*16 + br, kb + bkh)]);
                ldmx4(Bl[np], &sWl[swz(n0 + np*16 + br, kb + bkh)]);
            }
            #pragma unroll
            for (int mt = 0; mt < 2; mt++)
                #pragma unroll
                for (int nt = 0; nt < 4; nt++) {
                    const int np = nt >> 1, pr = (nt & 1) * 2;
                    mma16816(acc[mt][nt], Ah[mt], Bh[np][pr], Bh[np][pr+1]);
                    mma16816(acc[mt][nt], Al[mt], Bh[np][pr], Bh[np][pr+1]);
                    mma16816(acc[mt][nt], Ah[mt], Bl[np][pr], Bl[np][pr+1]);
                }
        }
        __syncthreads();
    }

    // epilogue: mma C fragment -> rows lane>>2 (+8), cols (lane&3)*2 (+1)
    #pragma unroll
    for (int mt = 0; mt < 2; mt++) {
        const int r = bm + m0 + mt*16 + (lane >> 2);
        #pragma unroll
        for (int nt = 0; nt < 4; nt++) {
            const int c = bn + n0 + nt*8 + (lane & 3) * 2;
            const float b0 = bias[c], b1 = bias[c + 1];
            *(float2*)(C + (size_t)r * DIMC + c) =
                make_float2(acc[mt][nt][0] + b0, acc[mt][nt][1] + b1);
            *(float2*)(C + (size_t)(r + 8) * DIMC + c) =
                make_float2(acc[mt][nt][2] + b0, acc[mt][nt][3] + b1);
        }
    }
}

// ============================================================================
// Flash attention per (b, h, 64-query tile) — unchanged from R6 (passing).
// ============================================================================
__global__ __launch_bounds__(256)
void attn_k()
{
    __shared__ __align__(16) float Qt[64*64];
    __shared__ __align__(16) float KtPs[64*64];
    __shared__ __align__(16) float Vs[64*64];

    const int b  = blockIdx.z;
    const int h  = blockIdx.y;
    const int q0 = blockIdx.x * 64;
    const int tid = threadIdx.x;
    const int tr = tid >> 4;
    const int tc = tid & 15;

    const float scale = 0.125f;   // HEAD_DIM^-0.5
    const float* Qg = g_q + (size_t)(b*SEQL + q0)*DIMC + h*HDIM;
    const float* Kg = g_k + (size_t)(b*SEQL)*DIMC + h*HDIM;
    const float* Vg = g_v + (size_t)(b*SEQL)*DIMC + h*HDIM;

    #pragma unroll
    for (int l = 0; l < 4; l++) {
        int idx = tid + l*256;
        int row = idx >> 4, dq = idx & 15;
        float4 qv = *(const float4*)(Qg + (size_t)row*DIMC + dq*4);
        int sw = row ^ (dq*4);
        Qt[(dq*4+0)*64+sw]=qv.x; Qt[(dq*4+1)*64+sw]=qv.y;
        Qt[(dq*4+2)*64+sw]=qv.z; Qt[(dq*4+3)*64+sw]=qv.w;
    }

    float m_run[4], l_run[4];
    ull oacc[4][2];
    #pragma unroll
    for (int i = 0; i < 4; i++) {
        m_run[i] = -1e30f; l_run[i] = 0.f; oacc[i][0] = 0; oacc[i][1] = 0;
    }

    for (int t0 = 0; t0 < SEQL; t0 += 64) {
        __syncthreads();
        #pragma unroll
        for (int l = 0; l < 4; l++) {
            int idx = tid + l*256;
            int row = idx >> 4, dq = idx & 15;
            float4 kv = *(const float4*)(Kg + (size_t)(t0+row)*DIMC + dq*4);
            int sw = row ^ (dq*4);
            KtPs[(dq*4+0)*64+sw]=kv.x; KtPs[(dq*4+1)*64+sw]=kv.y;
            KtPs[(dq*4+2)*64+sw]=kv.z; KtPs[(dq*4+3)*64+sw]=kv.w;
            float4 vv = *(const float4*)(Vg + (size_t)(t0+row)*DIMC + dq*4);
            *(float4*)&Vs[row*64 + dq*4] = vv;
        }
        __syncthreads();

        ull sacc[4][2];
        #pragma unroll
        for (int i = 0; i < 4; i++) { sacc[i][0]=0; sacc[i][1]=0; }
        #pragma unroll 4
        for (int d = 0; d < 64; d++) {
            int swzd = d & 60;
            float4 qv = *(const float4*)&Qt  [d*64 + ((tr*4) ^ swzd)];
            float4 kv = *(const float4*)&KtPs[d*64 + ((tc*4) ^ swzd)];
            ull k01 = pk2(kv.x, kv.y), k23 = pk2(kv.z, kv.w);
            float qa[4] = {qv.x, qv.y, qv.z, qv.w};
            #pragma unroll
            for (int i = 0; i < 4; i++) {
                ull q2 = pk2(qa[i], qa[i]);
                ffma2(sacc[i][0], q2, k01);
                ffma2(sacc[i][1], q2, k23);
            }
        }
        __syncthreads();

        float p[4][4];
        #pragma unroll
        for (int i = 0; i < 4; i++) {
            float s0,s1,s2,s3;
            upk2(sacc[i][0],s0,s1); upk2(sacc[i][1],s2,s3);
            s0*=scale; s1*=scale; s2*=scale; s3*=scale;
            float mloc = fmaxf(fmaxf(s0,s1), fmaxf(s2,s3));
            #pragma unroll
            for (int sft = 1; sft < 16; sft <<= 1)
                mloc = fmaxf(mloc, __shfl_xor_sync(0xffffffffu, mloc, sft, 16));
            float m_new = fmaxf(m_run[i], mloc);
            float alpha = __expf(m_run[i] - m_new);
            p[i][0]=__expf(s0-m_new); p[i][1]=__expf(s1-m_new);
            p[i][2]=__expf(s2-m_new); p[i][3]=__expf(s3-m_new);
            float lloc = p[i][0]+p[i][1]+p[i][2]+p[i][3];
            #pragma unroll
            for (int sft = 1; sft < 16; sft <<= 1)
                lloc += __shfl_xor_sync(0xffffffffu, lloc, sft, 16);
            l_run[i] = l_run[i]*alpha + lloc;
            m_run[i] = m_new;
            ull a2 = pk2(alpha, alpha);
            fmul2(oacc[i][0], a2);
            fmul2(oacc[i][1], a2);
            *(float4*)&KtPs[(tr*4+i)*64 + tc*4] =
                make_float4(p[i][0], p[i][1], p[i][2], p[i][3]);
        }
        __syncthreads();

        #pragma unroll 2
        for (int kc = 0; kc < 64; kc += 4) {
            float4 v0 = *(const float4*)&Vs[(kc+0)*64 + tc*4];
            float4 v1 = *(const float4*)&Vs[(kc+1)*64 + tc*4];
            float4 v2 = *(const float4*)&Vs[(kc+2)*64 + tc*4];
            float4 v3 = *(const float4*)&Vs[(kc+3)*64 + tc*4];
            ull v0a=pk2(v0.x,v0.y), v0b=pk2(v0.z,v0.w);
            ull v1a=pk2(v1.x,v1.y), v1b=pk2(v1.z,v1.w);
            ull v2a=pk2(v2.x,v2.y), v2b=pk2(v2.z,v2.w);
            ull v3a=pk2(v3.x,v3.y), v3b=pk2(v3.z,v3.w);
            #pragma unroll
            for (int i = 0; i < 4; i++) {
                float4 pv = *(const float4*)&KtPs[(tr*4+i)*64 + kc];
                ull p0=pk2(pv.x,pv.x), p1=pk2(pv.y,pv.y);
                ull p2=pk2(pv.z,pv.z), p3=pk2(pv.w,pv.w);
                ffma2(oacc[i][0], p0, v0a); ffma2(oacc[i][1], p0, v0b);
                ffma2(oacc[i][0], p1, v1a); ffma2(oacc[i][1], p1, v1b);
                ffma2(oacc[i][0], p2, v2a); ffma2(oacc[i][1], p2, v2b);
                ffma2(oacc[i][0], p3, v3a); ffma2(oacc[i][1], p3, v3b);
            }
        }
    }

    #pragma unroll
    for (int i = 0; i < 4; i++) {
        float inv = 1.0f / l_run[i];
        float x0,x1,x2,x3;
        upk2(oacc[i][0],x0,x1); upk2(oacc[i][1],x2,x3);
        size_t off = (size_t)(b*SEQL + q0 + tr*4 + i)*DIMC + h*HDIM + tc*4;
        *(float4*)(g_attn + off) = make_float4(x0*inv, x1*inv, x2*inv, x3*inv);
    }
}

extern "C" void kernel_launch(void* const* d_in, const int* in_sizes, int n_in,
                              void* d_out, int out_size)
{
    const float* x   = (const float*)d_in[0];
    const float* ctx = (const float*)d_in[1];
    const float* Wq  = (const float*)d_in[2];
    const float* bq  = (const float*)d_in[3];
    const float* Wk  = (const float*)d_in[4];
    const float* bk  = (const float*)d_in[5];
    const float* Wv  = (const float*)d_in[6];
    const float* bv  = (const float*)d_in[7];
    const float* Wo  = (const float*)d_in[8];
    const float* bo  = (const float*)d_in[9];
    float* out = (float*)d_out;

    dim3 gg(DIMC / TBN, NROWS / TBM);      // (8, 64)
    gemm_tc<<<gg, 512>>>(x,   Wq, bq, nullptr, 0, 0);   // Q
    gemm_tc<<<gg, 512>>>(ctx, Wk, bk, nullptr, 0, 1);   // K
    gemm_tc<<<gg, 512>>>(ctx, Wv, bv, nullptr, 0, 2);   // V
    attn_k<<<dim3(SEQL/64, NHEADS, BATCH), 256>>>();    // flash attention
    gemm_tc<<<gg, 512>>>(nullptr, Wo, bo, out, 1, 3);   // O projection
}

// round 10
// speedup vs baseline: 2.9361x; 2.4063x over previous
#include <cuda_runtime.h>
#include <cuda_bf16.h>
#include <cuda_fp16.h>
#include <cstdint>

#define DIMC   1024
#define BATCH  4
#define SEQL   2048
#define NHEADS 16
#define HDIM   64
#define NROWS  (BATCH*SEQL)   // 8192

typedef unsigned long long ull;

// ---- scratch: __device__ globals (no cudaMalloc anywhere) -------------------
__device__ __align__(16) float g_q[NROWS*DIMC];
__device__ __align__(16) float g_k[NROWS*DIMC];
__device__ __align__(16) float g_v[NROWS*DIMC];
__device__ __align__(16) float g_attn[NROWS*DIMC];

// ============================================================================
// Tensor-core GEMM with bf16x3 split — unchanged from R8 (passing, ~194us ea).
// ============================================================================
#define TBM 128
#define TBN 128
#define TBK 32

__device__ __forceinline__ int swz(int row, int k) {
    return row * TBK + ((((k >> 3) ^ (row >> 1)) & 3) << 3) + (k & 7);
}

__device__ __forceinline__ void ldmx4(uint32_t* r, const void* p) {
    uint32_t a = (uint32_t)__cvta_generic_to_shared(p);
    asm volatile("ldmatrix.sync.aligned.m8n8.x4.shared.b16 {%0,%1,%2,%3}, [%4];"
        : "=r"(r[0]), "=r"(r[1]), "=r"(r[2]), "=r"(r[3]) : "r"(a));
}

__device__ __forceinline__ void ldmx4t(uint32_t* r, const void* p) {
    uint32_t a = (uint32_t)__cvta_generic_to_shared(p);
    asm volatile("ldmatrix.sync.aligned.m8n8.x4.trans.shared.b16 {%0,%1,%2,%3}, [%4];"
        : "=r"(r[0]), "=r"(r[1]), "=r"(r[2]), "=r"(r[3]) : "r"(a));
}

__device__ __forceinline__ void mma16816(float* c, const uint32_t* a,
                                         uint32_t b0, uint32_t b1) {
    asm volatile(
        "mma.sync.aligned.m16n8k16.row.col.f32.bf16.bf16.f32 "
        "{%0,%1,%2,%3}, {%4,%5,%6,%7}, {%8,%9}, {%0,%1,%2,%3};"
        : "+f"(c[0]), "+f"(c[1]), "+f"(c[2]), "+f"(c[3])
        : "r"(a[0]), "r"(a[1]), "r"(a[2]), "r"(a[3]), "r"(b0), "r"(b1));
}

__device__ __forceinline__ void mmaf16(float* c, const uint32_t* a,
                                       uint32_t b0, uint32_t b1) {
    asm volatile(
        "mma.sync.aligned.m16n8k16.row.col.f32.f16.f16.f32 "
        "{%0,%1,%2,%3}, {%4,%5,%6,%7}, {%8,%9}, {%0,%1,%2,%3};"
        : "+f"(c[0]), "+f"(c[1]), "+f"(c[2]), "+f"(c[3])
        : "r"(a[0]), "r"(a[1]), "r"(a[2]), "r"(a[3]), "r"(b0), "r"(b1));
}

__device__ __forceinline__ void split4(float4 v, ull& hi, ull& lo) {
    union { __nv_bfloat16 b[4]; ull u; } H, L;
    float x[4] = {v.x, v.y, v.z, v.w};
    #pragma unroll
    for (int i = 0; i < 4; i++) {
        __nv_bfloat16 h = __float2bfloat16(x[i]);
        H.b[i] = h;
        L.b[i] = __float2bfloat16(x[i] - __bfloat162float(h));
    }
    hi = H.u; lo = L.u;
}

__global__ __launch_bounds__(512, 1)
void gemm_tc(const float* __restrict__ Aext, const float* __restrict__ W,
             const float* __restrict__ bias, float* __restrict__ Cext,
             int asel, int csel)
{
    __shared__ __align__(16) __nv_bfloat16 sAh[TBM*TBK];
    __shared__ __align__(16) __nv_bfloat16 sAl[TBM*TBK];
    __shared__ __align__(16) __nv_bfloat16 sWh[TBN*TBK];
    __shared__ __align__(16) __nv_bfloat16 sWl[TBN*TBK];

    const float* A = (asel == 1) ? (const float*)g_attn : Aext;
    float* C = (csel == 0) ? (float*)g_q : (csel == 1) ? (float*)g_k
             : (csel == 2) ? (float*)g_v : Cext;

    const int bm = blockIdx.y * TBM;
    const int bn = blockIdx.x * TBN;
    const int tid  = threadIdx.x;
    const int wid  = tid >> 5;
    const int lane = tid & 31;
    const int m0 = (wid >> 2) * 32;
    const int n0 = (wid & 3) * 32;
    const int lrow = tid >> 3;
    const int lkq  = tid & 7;

    float acc[2][4][4];
    #pragma unroll
    for (int a = 0; a < 2; a++)
        #pragma unroll
        for (int b = 0; b < 4; b++)
            #pragma unroll
            for (int c = 0; c < 4; c++) acc[a][b][c] = 0.f;

    float4 aP0, aP1, wP0, wP1;
    {
        const float* Ap = A + (size_t)(bm + lrow) * DIMC + lkq * 4;
        const float* Wp = W + (size_t)(bn + lrow) * DIMC + lkq * 4;
        aP0 = *(const float4*)Ap;  aP1 = *(const float4*)(Ap + (size_t)64*DIMC);
        wP0 = *(const float4*)Wp;  wP1 = *(const float4*)(Wp + (size_t)64*DIMC);
    }

    const int ar  = lane & 15;
    const int akh = (lane >> 4) * 8;
    const int br  = (lane & 7) + ((lane >> 4) << 3);
    const int bkh = ((lane >> 3) & 1) * 8;

    for (int k0 = 0; k0 < DIMC; k0 += TBK) {
        {
            ull h, l;
            split4(aP0, h, l);
            *(ull*)&sAh[swz(lrow,      lkq*4)] = h;
            *(ull*)&sAl[swz(lrow,      lkq*4)] = l;
            split4(aP1, h, l);
            *(ull*)&sAh[swz(lrow + 64, lkq*4)] = h;
            *(ull*)&sAl[swz(lrow + 64, lkq*4)] = l;
            split4(wP0, h, l);
            *(ull*)&sWh[swz(lrow,      lkq*4)] = h;
            *(ull*)&sWl[swz(lrow,      lkq*4)] = l;
            split4(wP1, h, l);
            *(ull*)&sWh[swz(lrow + 64, lkq*4)] = h;
            *(ull*)&sWl[swz(lrow + 64, lkq*4)] = l;
        }
        __syncthreads();

        if (k0 + TBK < DIMC) {
            const float* Ap = A + (size_t)(bm + lrow) * DIMC + (k0 + TBK) + lkq * 4;
            const float* Wp = W + (size_t)(bn + lrow) * DIMC + (k0 + TBK) + lkq * 4;
            aP0 = *(const float4*)Ap;  aP1 = *(const float4*)(Ap + (size_t)64*DIMC);
            wP0 = *(const float4*)Wp;  wP1 = *(const float4*)(Wp + (size_t)64*DIMC);
        }

        #pragma unroll
        for (int kk = 0; kk < 2; kk++) {
            const int kb = kk * 16;
            uint32_t Ah[2][4], Al[2][4], Bh[2][4], Bl[2][4];
            #pragma unroll
            for (int mt = 0; mt < 2; mt++) {
                ldmx4(Ah[mt], &sAh[swz(m0 + mt*16 + ar, kb + akh)]);
                ldmx4(Al[mt], &sAl[swz(m0 + mt*16 + ar, kb + akh)]);
            }
            #pragma unroll
            for (int np = 0; np < 2; np++) {
                ldmx4(Bh[np], &sWh[swz(n0 + np*16 + br, kb + bkh)]);
                ldmx4(Bl[np], &sWl[swz(n0 + np*16 + br, kb + bkh)]);
            }
            #pragma unroll
            for (int mt = 0; mt < 2; mt++)
                #pragma unroll
                for (int nt = 0; nt < 4; nt++) {
                    const int np = nt >> 1, pr = (nt & 1) * 2;
                    mma16816(acc[mt][nt], Ah[mt], Bh[np][pr], Bh[np][pr+1]);
                    mma16816(acc[mt][nt], Al[mt], Bh[np][pr], Bh[np][pr+1]);
                    mma16816(acc[mt][nt], Ah[mt], Bl[np][pr], Bl[np][pr+1]);
                }
        }
        __syncthreads();
    }

    #pragma unroll
    for (int mt = 0; mt < 2; mt++) {
        const int r = bm + m0 + mt*16 + (lane >> 2);
        #pragma unroll
        for (int nt = 0; nt < 4; nt++) {
            const int c = bn + n0 + nt*8 + (lane & 3) * 2;
            const float b0 = bias[c], b1 = bias[c + 1];
            *(float2*)(C + (size_t)r * DIMC + c) =
                make_float2(acc[mt][nt][0] + b0, acc[mt][nt][1] + b1);
            *(float2*)(C + (size_t)(r + 8) * DIMC + c) =
                make_float2(acc[mt][nt][2] + b0, acc[mt][nt][3] + b1);
        }
    }
}

// ============================================================================
// Tensor-core flash attention (fp16 single-pass, fp32 accumulate).
// Block = 128 queries, 8 warps (warp = 16 q-rows x 64 keys). Key tile 64.
// Smem: sQ[128x64] (persistent) + sK[64x64] + sV[64x64], fp16, 32KB total.
// Swizzle: 16B chunk c at row r lives at chunk (c ^ (r&7)) -> conflict-free
// STS (8 lanes per row = full 128B line) and ldmatrix (8 rows, distinct chunks).
// S C-fragments ARE PV A-fragments (register identity) -> P never hits smem.
// ============================================================================
__device__ __forceinline__ uint32_t pack_h2(float lo, float hi) {
    uint32_t r;
    asm("cvt.rn.f16x2.f32 %0, %1, %2;" : "=r"(r) : "f"(hi), "f"(lo));
    return r;
}

// load 8 fp32 from gmem, scale, convert, store 16B swizzled
__device__ __forceinline__ void cvt_store8(char* sbase, const float* src,
                                           int row, int seg, float scale) {
    float4 f0 = *(const float4*)src;
    float4 f1 = *(const float4*)(src + 4);
    __half2 h0 = __floats2half2_rn(f0.x*scale, f0.y*scale);
    __half2 h1 = __floats2half2_rn(f0.z*scale, f0.w*scale);
    __half2 h2 = __floats2half2_rn(f1.x*scale, f1.y*scale);
    __half2 h3 = __floats2half2_rn(f1.z*scale, f1.w*scale);
    uint4 u;
    u.x = *(uint32_t*)&h0; u.y = *(uint32_t*)&h1;
    u.z = *(uint32_t*)&h2; u.w = *(uint32_t*)&h3;
    *(uint4*)(sbase + row*128 + ((seg ^ (row & 7)) * 16)) = u;
}

__global__ __launch_bounds__(256, 2)
void attn_tc()
{
    __shared__ __align__(16) __half sQ[128*64];
    __shared__ __align__(16) __half sK[64*64];
    __shared__ __align__(16) __half sV[64*64];

    const int b  = blockIdx.z;
    const int h  = blockIdx.y;
    const int q0 = blockIdx.x * 128;
    const int tid  = threadIdx.x;
    const int wid  = tid >> 5;
    const int lane = tid & 31;

    const float* Qg = g_q + (size_t)(b*SEQL + q0)*DIMC + h*HDIM;
    const float* Kg = g_k + (size_t)(b*SEQL)*DIMC + h*HDIM;
    const float* Vg = g_v + (size_t)(b*SEQL)*DIMC + h*HDIM;

    // ---- load Q (scale 0.125 folded in) ----
    #pragma unroll
    for (int l = 0; l < 4; l++) {
        int u = tid + l*256;
        int row = u >> 3, seg = u & 7;
        cvt_store8((char*)sQ, Qg + (size_t)row*DIMC + seg*8, row, seg, 0.125f);
    }
    __syncthreads();

    // ---- hoist Q fragments into registers (warp rows wid*16..+15) ----
    uint32_t qf[4][4];
    {
        int r = wid*16 + (lane & 15);
        char* rb = (char*)sQ + r*128;
        int rx = r & 7;
        #pragma unroll
        for (int ks = 0; ks < 4; ks++) {
            int c = ks*2 + (lane >> 4);
            ldmx4(qf[ks], rb + ((c ^ rx) * 16));
        }
    }

    // fragment address components
    const int krow_off = (lane & 7) + ((lane >> 4) * 8);  // key within 16-block
    const int kd_sub   = (lane >> 3) & 1;                 // d-chunk +1 selector
    const int vrow_off = lane & 15;                       // key within 16-block
    const int vd_sub   = lane >> 4;                       // d-chunk +1 selector

    float m0 = -1e30f, m1 = -1e30f, l0 = 0.f, l1 = 0.f;
    float oacc[8][4];
    #pragma unroll
    for (int t = 0; t < 8; t++) { oacc[t][0]=0.f; oacc[t][1]=0.f; oacc[t][2]=0.f; oacc[t][3]=0.f; }

    for (int t0 = 0; t0 < SEQL; t0 += 64) {
        __syncthreads();   // prev tile's mma reads done
        #pragma unroll
        for (int l = 0; l < 2; l++) {
            int u = tid + l*256;
            int row = u >> 3, seg = u & 7;
            cvt_store8((char*)sK, Kg + (size_t)(t0+row)*DIMC + seg*8, row, seg, 1.f);
            cvt_store8((char*)sV, Vg + (size_t)(t0+row)*DIMC + seg*8, row, seg, 1.f);
        }
        __syncthreads();

        // ---- S = Q K^T : sacc[8 n-tiles][4] ----
        float sacc[8][4];
        #pragma unroll
        for (int t = 0; t < 8; t++) { sacc[t][0]=0.f; sacc[t][1]=0.f; sacc[t][2]=0.f; sacc[t][3]=0.f; }
        #pragma unroll
        for (int ks = 0; ks < 4; ks++) {
            uint32_t kf[4][4];
            #pragma unroll
            for (int nb = 0; nb < 4; nb++) {
                int key = nb*16 + krow_off;
                int c = ks*2 + kd_sub;
                ldmx4(kf[nb], (char*)sK + key*128 + ((c ^ (key & 7)) * 16));
            }
            #pragma unroll
            for (int nb = 0; nb < 4; nb++) {
                mmaf16(sacc[2*nb],   qf[ks], kf[nb][0], kf[nb][1]);
                mmaf16(sacc[2*nb+1], qf[ks], kf[nb][2], kf[nb][3]);
            }
        }

        // ---- online softmax (rows lane>>2 and +8; 4 lanes share a row) ----
        float mx0 = -1e30f, mx1 = -1e30f;
        #pragma unroll
        for (int t = 0; t < 8; t++) {
            mx0 = fmaxf(mx0, fmaxf(sacc[t][0], sacc[t][1]));
            mx1 = fmaxf(mx1, fmaxf(sacc[t][2], sacc[t][3]));
        }
        mx0 = fmaxf(mx0, __shfl_xor_sync(0xffffffffu, mx0, 1));
        mx0 = fmaxf(mx0, __shfl_xor_sync(0xffffffffu, mx0, 2));
        mx1 = fmaxf(mx1, __shfl_xor_sync(0xffffffffu, mx1, 1));
        mx1 = fmaxf(mx1, __shfl_xor_sync(0xffffffffu, mx1, 2));
        float mn0 = fmaxf(m0, mx0), mn1 = fmaxf(m1, mx1);
        float al0 = __expf(m0 - mn0), al1 = __expf(m1 - mn1);
        float ls0 = 0.f, ls1 = 0.f;
        #pragma unroll
        for (int t = 0; t < 8; t++) {
            sacc[t][0] = __expf(sacc[t][0] - mn0);
            sacc[t][1] = __expf(sacc[t][1] - mn0);
            sacc[t][2] = __expf(sacc[t][2] - mn1);
            sacc[t][3] = __expf(sacc[t][3] - mn1);
            ls0 += sacc[t][0] + sacc[t][1];
            ls1 += sacc[t][2] + sacc[t][3];
        }
        ls0 += __shfl_xor_sync(0xffffffffu, ls0, 1);
        ls0 += __shfl_xor_sync(0xffffffffu, ls0, 2);
        ls1 += __shfl_xor_sync(0xffffffffu, ls1, 1);
        ls1 += __shfl_xor_sync(0xffffffffu, ls1, 2);
        l0 = l0*al0 + ls0;  m0 = mn0;
        l1 = l1*al1 + ls1;  m1 = mn1;
        #pragma unroll
        for (int t = 0; t < 8; t++) {
            oacc[t][0] *= al0; oacc[t][1] *= al0;
            oacc[t][2] *= al1; oacc[t][3] *= al1;
        }

        // ---- O += P V (P from S fragments, register identity) ----
        #pragma unroll
        for (int j = 0; j < 4; j++) {
            uint32_t a[4];
            a[0] = pack_h2(sacc[2*j][0],   sacc[2*j][1]);
            a[1] = pack_h2(sacc[2*j][2],   sacc[2*j][3]);
            a[2] = pack_h2(sacc[2*j+1][0], sacc[2*j+1][1]);
            a[3] = pack_h2(sacc[2*j+1][2], sacc[2*j+1][3]);
            uint32_t vf[4][4];
            #pragma unroll
            for (int nb = 0; nb < 4; nb++) {
                int row = j*16 + vrow_off;
                int c = nb*2 + vd_sub;
                ldmx4t(vf[nb], (char*)sV + row*128 + ((c ^ (row & 7)) * 16));
            }
            #pragma unroll
            for (int nb = 0; nb < 4; nb++) {
                mmaf16(oacc[2*nb],   a, vf[nb][0], vf[nb][1]);
                mmaf16(oacc[2*nb+1], a, vf[nb][2], vf[nb][3]);
            }
        }
    }

    // ---- normalize + write [B,N,H*D] fp32 into g_attn ----
    const float inv0 = 1.0f / l0, inv1 = 1.0f / l1;
    const int r = q0 + wid*16 + (lane >> 2);
    const size_t base0 = (size_t)(b*SEQL + r) * DIMC + h*HDIM + (lane & 3)*2;
    const size_t base1 = base0 + (size_t)8 * DIMC;
    #pragma unroll
    for (int t = 0; t < 8; t++) {
        *(float2*)(g_attn + base0 + t*8) =
            make_float2(oacc[t][0]*inv0, oacc[t][1]*inv0);
        *(float2*)(g_attn + base1 + t*8) =
            make_float2(oacc[t][2]*inv1, oacc[t][3]*inv1);
    }
}

extern "C" void kernel_launch(void* const* d_in, const int* in_sizes, int n_in,
                              void* d_out, int out_size)
{
    const float* x   = (const float*)d_in[0];
    const float* ctx = (const float*)d_in[1];
    const float* Wq  = (const float*)d_in[2];
    const float* bq  = (const float*)d_in[3];
    const float* Wk  = (const float*)d_in[4];
    const float* bk  = (const float*)d_in[5];
    const float* Wv  = (const float*)d_in[6];
    const float* bv  = (const float*)d_in[7];
    const float* Wo  = (const float*)d_in[8];
    const float* bo  = (const float*)d_in[9];
    float* out = (float*)d_out;

    dim3 gg(DIMC / TBN, NROWS / TBM);      // (8, 64)
    gemm_tc<<<gg, 512>>>(x,   Wq, bq, nullptr, 0, 0);   // Q
    gemm_tc<<<gg, 512>>>(ctx, Wk, bk, nullptr, 0, 1);   // K
    gemm_tc<<<gg, 512>>>(ctx, Wv, bv, nullptr, 0, 2);   // V
    attn_tc<<<dim3(SEQL/128, NHEADS, BATCH), 256>>>();  // fp16 TC flash attn
    gemm_tc<<<gg, 512>>>(nullptr, Wo, bo, out, 1, 3);   // O projection
}

// round 11
// speedup vs baseline: 3.6880x; 1.2561x over previous
#include <cuda_runtime.h>
#include <cuda_bf16.h>
#include <cuda_fp16.h>
#include <cstdint>

#define DIMC   1024
#define BATCH  4
#define SEQL   2048
#define NHEADS 16
#define HDIM   64
#define NROWS  (BATCH*SEQL)   // 8192

typedef unsigned long long ull;

// ---- scratch: __device__ globals (no cudaMalloc anywhere) -------------------
// pre-split bf16 operands (hi/lo) for the GEMMs
__device__ __align__(16) __nv_bfloat16 g_xh[NROWS*DIMC], g_xl[NROWS*DIMC];
__device__ __align__(16) __nv_bfloat16 g_ch[NROWS*DIMC], g_cl[NROWS*DIMC];
__device__ __align__(16) __nv_bfloat16 g_wqh[DIMC*DIMC], g_wql[DIMC*DIMC];
__device__ __align__(16) __nv_bfloat16 g_wkh[DIMC*DIMC], g_wkl[DIMC*DIMC];
__device__ __align__(16) __nv_bfloat16 g_wvh[DIMC*DIMC], g_wvl[DIMC*DIMC];
__device__ __align__(16) __nv_bfloat16 g_woh[DIMC*DIMC], g_wol[DIMC*DIMC];
// fp16 Q/K/V (Q pre-scaled by 0.125) and bf16-split attention output
__device__ __align__(16) __half        g_qh[NROWS*DIMC];
__device__ __align__(16) __half        g_kh[NROWS*DIMC];
__device__ __align__(16) __half        g_vh[NROWS*DIMC];
__device__ __align__(16) __nv_bfloat16 g_aoh[NROWS*DIMC], g_aol[NROWS*DIMC];

// ---- common helpers ---------------------------------------------------------
__device__ __forceinline__ void split4(float4 v, ull& hi, ull& lo) {
    union { __nv_bfloat16 b[4]; ull u; } H, L;
    float x[4] = {v.x, v.y, v.z, v.w};
    #pragma unroll
    for (int i = 0; i < 4; i++) {
        __nv_bfloat16 h = __float2bfloat16(x[i]);
        H.b[i] = h;
        L.b[i] = __float2bfloat16(x[i] - __bfloat162float(h));
    }
    hi = H.u; lo = L.u;
}

__device__ __forceinline__ void cpa16(void* dst, const void* src) {
    uint32_t d = (uint32_t)__cvta_generic_to_shared(dst);
    asm volatile("cp.async.cg.shared.global [%0], [%1], 16;" :: "r"(d), "l"(src));
}
#define CP_COMMIT() asm volatile("cp.async.commit_group;")
template <int N>
__device__ __forceinline__ void cp_wait() {
    asm volatile("cp.async.wait_group %0;" :: "n"(N));
}

__device__ __forceinline__ void ldmx4(uint32_t* r, const void* p) {
    uint32_t a = (uint32_t)__cvta_generic_to_shared(p);
    asm volatile("ldmatrix.sync.aligned.m8n8.x4.shared.b16 {%0,%1,%2,%3}, [%4];"
        : "=r"(r[0]), "=r"(r[1]), "=r"(r[2]), "=r"(r[3]) : "r"(a));
}
__device__ __forceinline__ void ldmx4t(uint32_t* r, const void* p) {
    uint32_t a = (uint32_t)__cvta_generic_to_shared(p);
    asm volatile("ldmatrix.sync.aligned.m8n8.x4.trans.shared.b16 {%0,%1,%2,%3}, [%4];"
        : "=r"(r[0]), "=r"(r[1]), "=r"(r[2]), "=r"(r[3]) : "r"(a));
}
__device__ __forceinline__ void mma16816(float* c, const uint32_t* a,
                                         uint32_t b0, uint32_t b1) {
    asm volatile(
        "mma.sync.aligned.m16n8k16.row.col.f32.bf16.bf16.f32 "
        "{%0,%1,%2,%3}, {%4,%5,%6,%7}, {%8,%9}, {%0,%1,%2,%3};"
        : "+f"(c[0]), "+f"(c[1]), "+f"(c[2]), "+f"(c[3])
        : "r"(a[0]), "r"(a[1]), "r"(a[2]), "r"(a[3]), "r"(b0), "r"(b1));
}
__device__ __forceinline__ void mmaf16(float* c, const uint32_t* a,
                                       uint32_t b0, uint32_t b1) {
    asm volatile(
        "mma.sync.aligned.m16n8k16.row.col.f32.f16.f16.f32 "
        "{%0,%1,%2,%3}, {%4,%5,%6,%7}, {%8,%9}, {%0,%1,%2,%3};"
        : "+f"(c[0]), "+f"(c[1]), "+f"(c[2]), "+f"(c[3])
        : "r"(a[0]), "r"(a[1]), "r"(a[2]), "r"(a[3]), "r"(b0), "r"(b1));
}
__device__ __forceinline__ uint32_t pack_h2(float lo, float hi) {
    uint32_t r;
    asm("cvt.rn.f16x2.f32 %0, %1, %2;" : "=r"(r) : "f"(hi), "f"(lo));
    return r;
}

// ============================================================================
// One-shot split: fp32 -> bf16 hi/lo into selected scratch pair.
// dsel: 0=x, 1=ctx, 2=Wq, 3=Wk, 4=Wv, 5=Wo
// ============================================================================
__global__ void split_k(const float* __restrict__ src, int dsel, int n4)
{
    __nv_bfloat16 *hi, *lo;
    switch (dsel) {
        case 0: hi = g_xh;  lo = g_xl;  break;
        case 1: hi = g_ch;  lo = g_cl;  break;
        case 2: hi = g_wqh; lo = g_wql; break;
        case 3: hi = g_wkh; lo = g_wkl; break;
        case 4: hi = g_wvh; lo = g_wvl; break;
        default: hi = g_woh; lo = g_wol; break;
    }
    int i = blockIdx.x * blockDim.x + threadIdx.x;
    if (i >= n4) return;
    float4 v = ((const float4*)src)[i];
    ull h, l; split4(v, h, l);
    ((ull*)hi)[i] = h;
    ((ull*)lo)[i] = l;
}

// ============================================================================
// GEMM on pre-split bf16: C[r,o] = sum_k A[r,k]*W[o,k] + bias[o]
// 128x128x32 tiles, 512 threads, warp tile 32x32, bf16x3 triple.
// cp.async double-buffered smem (2 x 32KB, dynamic). No split in hot loop.
// asel: 0=x, 1=ctx, 2=attn-out.  wsel: 0..3 = Wq/Wk/Wv/Wo.
// osel: 0/1/2 -> g_qh/g_kh/g_vh (fp16, *oscale), 3 -> Cext fp32.
// ============================================================================
#define TBM 128
#define TBN 128
#define TBK 32
#define STG 32768          // bytes per stage (Ah|Al|Wh|Wl, 8KB each)

// byte offset inside an 8KB [128 x 32] bf16 tile, XOR-swizzled (k multiple of 8)
__device__ __forceinline__ int toff(int row, int k) {
    return row * 64 + ((((k >> 3) ^ ((row >> 1) & 3)) & 3) << 4);
}

extern __shared__ char dynsmem[];

__global__ __launch_bounds__(512, 1)
void gemm_tc2(const float* __restrict__ bias, float* __restrict__ Cext,
              int asel, int wsel, int osel, float oscale)
{
    const __nv_bfloat16 *Ah, *Al, *Wh, *Wl;
    switch (asel) {
        case 0: Ah = g_xh;  Al = g_xl;  break;
        case 1: Ah = g_ch;  Al = g_cl;  break;
        default: Ah = g_aoh; Al = g_aol; break;
    }
    switch (wsel) {
        case 0: Wh = g_wqh; Wl = g_wql; break;
        case 1: Wh = g_wkh; Wl = g_wkl; break;
        case 2: Wh = g_wvh; Wl = g_wvl; break;
        default: Wh = g_woh; Wl = g_wol; break;
    }

    const int bm = blockIdx.y * TBM;
    const int bn = blockIdx.x * TBN;
    const int tid  = threadIdx.x;
    const int wid  = tid >> 5;
    const int lane = tid & 31;
    const int m0 = (wid >> 2) * 32;
    const int n0 = (wid & 3) * 32;

    // loader: thread -> one 16B chunk of each of the 4 tiles
    const int lrow = tid >> 2;          // 0..127
    const int lkc  = tid & 3;           // k-chunk 0..3 (8 bf16 each)
    const int ldst = toff(lrow, lkc * 8);
    const size_t lasrc = (size_t)(bm + lrow) * DIMC + lkc * 8;
    const size_t lwsrc = (size_t)(bn + lrow) * DIMC + lkc * 8;

    char* buf0 = dynsmem;
    char* buf1 = dynsmem + STG;

    auto issue = [&](int k0, char* bp) {
        cpa16(bp          + ldst, Ah + lasrc + k0);
        cpa16(bp + 8192   + ldst, Al + lasrc + k0);
        cpa16(bp + 16384  + ldst, Wh + lwsrc + k0);
        cpa16(bp + 24576  + ldst, Wl + lwsrc + k0);
    };

    float acc[2][4][4];
    #pragma unroll
    for (int a = 0; a < 2; a++)
        #pragma unroll
        for (int b = 0; b < 4; b++)
            #pragma unroll
            for (int c = 0; c < 4; c++) acc[a][b][c] = 0.f;

    const int ar  = lane & 15;
    const int akh = (lane >> 4) * 8;
    const int br  = (lane & 7) + ((lane >> 4) << 3);
    const int bkh = ((lane >> 3) & 1) * 8;

    issue(0, buf0);
    CP_COMMIT();

    const int NSLAB = DIMC / TBK;       // 32
    for (int i = 0; i < NSLAB; i++) {
        int nk = (i + 1 < NSLAB) ? (i + 1) : (NSLAB - 1);   // clamp (redundant)
        issue(nk * TBK, (i & 1) ? buf0 : buf1);
        CP_COMMIT();
        cp_wait<1>();
        __syncthreads();

        char* bp = (i & 1) ? buf1 : buf0;
        #pragma unroll
        for (int kk = 0; kk < 2; kk++) {
            const int kb = kk * 16;
            uint32_t Ahf[2][4], Alf[2][4], Bhf[2][4], Blf[2][4];
            #pragma unroll
            for (int mt = 0; mt < 2; mt++) {
                int o = toff(m0 + mt*16 + ar, kb + akh) + ((kb + akh) & 7) * 2;
                ldmx4(Ahf[mt], bp + o);
                ldmx4(Alf[mt], bp + 8192 + o);
            }
            #pragma unroll
            for (int np = 0; np < 2; np++) {
                int o = toff(n0 + np*16 + br, kb + bkh) + ((kb + bkh) & 7) * 2;
                ldmx4(Bhf[np], bp + 16384 + o);
                ldmx4(Blf[np], bp + 24576 + o);
            }
            #pragma unroll
            for (int mt = 0; mt < 2; mt++)
                #pragma unroll
                for (int nt = 0; nt < 4; nt++) {
                    const int np = nt >> 1, pr = (nt & 1) * 2;
                    mma16816(acc[mt][nt], Ahf[mt], Bhf[np][pr], Bhf[np][pr+1]);
                    mma16816(acc[mt][nt], Alf[mt], Bhf[np][pr], Bhf[np][pr+1]);
                    mma16816(acc[mt][nt], Ahf[mt], Blf[np][pr], Blf[np][pr+1]);
                }
        }
        __syncthreads();
    }

    // epilogue
    __half* Chalf = (osel == 0) ? g_qh : (osel == 1) ? g_kh : g_vh;
    #pragma unroll
    for (int mt = 0; mt < 2; mt++) {
        const int r = bm + m0 + mt*16 + (lane >> 2);
        #pragma unroll
        for (int nt = 0; nt < 4; nt++) {
            const int c = bn + n0 + nt*8 + (lane & 3) * 2;
            const float b0 = bias[c], b1 = bias[c + 1];
            if (osel < 3) {
                *(__half2*)(Chalf + (size_t)r * DIMC + c) =
                    __floats2half2_rn((acc[mt][nt][0] + b0) * oscale,
                                      (acc[mt][nt][1] + b1) * oscale);
                *(__half2*)(Chalf + (size_t)(r + 8) * DIMC + c) =
                    __floats2half2_rn((acc[mt][nt][2] + b0) * oscale,
                                      (acc[mt][nt][3] + b1) * oscale);
            } else {
                *(float2*)(Cext + (size_t)r * DIMC + c) =
                    make_float2(acc[mt][nt][0] + b0, acc[mt][nt][1] + b1);
                *(float2*)(Cext + (size_t)(r + 8) * DIMC + c) =
                    make_float2(acc[mt][nt][2] + b0, acc[mt][nt][3] + b1);
            }
        }
    }
}

// ============================================================================
// Tensor-core flash attention: fp16 in gmem (Q pre-scaled), cp.async loads,
// double-buffered K/V. Smem = sQ 16K + sK 2x8K + sV 2x8K = 48KB static.
// Epilogue writes bf16 hi/lo split (feeds O-GEMM directly).
// ============================================================================
__global__ __launch_bounds__(256, 2)
void attn_tc()
{
    __shared__ __align__(16) __half sQ[128*64];
    __shared__ __align__(16) __half sK[2][64*64];
    __shared__ __align__(16) __half sV[2][64*64];

    const int b  = blockIdx.z;
    const int h  = blockIdx.y;
    const int q0 = blockIdx.x * 128;
    const int tid  = threadIdx.x;
    const int wid  = tid >> 5;
    const int lane = tid & 31;

    const __half* Qg = g_qh + (size_t)(b*SEQL + q0)*DIMC + h*HDIM;
    const __half* Kg = g_kh + (size_t)(b*SEQL)*DIMC + h*HDIM;
    const __half* Vg = g_vh + (size_t)(b*SEQL)*DIMC + h*HDIM;

    auto issueKV = [&](int t0, int p) {
        #pragma unroll
        for (int l = 0; l < 2; l++) {
            int u = tid + l*256;
            int row = u >> 3, seg = u & 7;
            int so = row*128 + ((seg ^ (row & 7)) * 16);
            cpa16((char*)sK[p] + so, Kg + (size_t)(t0+row)*DIMC + seg*8);
            cpa16((char*)sV[p] + so, Vg + (size_t)(t0+row)*DIMC + seg*8);
        }
    };

    // prologue: Q + tile0 (group0), tile1 (group1)
    #pragma unroll
    for (int l = 0; l < 4; l++) {
        int u = tid + l*256;
        int row = u >> 3, seg = u & 7;
        cpa16((char*)sQ + row*128 + ((seg ^ (row & 7)) * 16),
              Qg + (size_t)row*DIMC + seg*8);
    }
    issueKV(0, 0);
    CP_COMMIT();
    issueKV(64, 1);
    CP_COMMIT();
    cp_wait<1>();       // Q + tile0 ready
    __syncthreads();

    // hoist Q fragments (warp rows wid*16..+15)
    uint32_t qf[4][4];
    {
        int r = wid*16 + (lane & 15);
        char* rb = (char*)sQ + r*128;
        int rx = r & 7;
        #pragma unroll
        for (int ks = 0; ks < 4; ks++) {
            int c = ks*2 + (lane >> 4);
            ldmx4(qf[ks], rb + ((c ^ rx) * 16));
        }
    }

    const int krow_off = (lane & 7) + ((lane >> 4) * 8);
    const int kd_sub   = (lane >> 3) & 1;
    const int vrow_off = lane & 15;
    const int vd_sub   = lane >> 4;

    float m0 = -1e30f, m1 = -1e30f, l0 = 0.f, l1 = 0.f;
    float oacc[8][4];
    #pragma unroll
    for (int t = 0; t < 8; t++) { oacc[t][0]=0.f; oacc[t][1]=0.f; oacc[t][2]=0.f; oacc[t][3]=0.f; }

    const int NT = SEQL / 64;   // 32
    for (int t = 0; t < NT; t++) {
        const int p = t & 1;

        // ---- S = Q K^T ----
        float sacc[8][4];
        #pragma unroll
        for (int u = 0; u < 8; u++) { sacc[u][0]=0.f; sacc[u][1]=0.f; sacc[u][2]=0.f; sacc[u][3]=0.f; }
        #pragma unroll
        for (int ks = 0; ks < 4; ks++) {
            uint32_t kf[4][4];
            #pragma unroll
            for (int nb = 0; nb < 4; nb++) {
                int key = nb*16 + krow_off;
                int c = ks*2 + kd_sub;
                ldmx4(kf[nb], (char*)sK[p] + key*128 + ((c ^ (key & 7)) * 16));
            }
            #pragma unroll
            for (int nb = 0; nb < 4; nb++) {
                mmaf16(sacc[2*nb],   qf[ks], kf[nb][0], kf[nb][1]);
                mmaf16(sacc[2*nb+1], qf[ks], kf[nb][2], kf[nb][3]);
            }
        }

        // ---- online softmax ----
        float mx0 = -1e30f, mx1 = -1e30f;
        #pragma unroll
        for (int u = 0; u < 8; u++) {
            mx0 = fmaxf(mx0, fmaxf(sacc[u][0], sacc[u][1]));
            mx1 = fmaxf(mx1, fmaxf(sacc[u][2], sacc[u][3]));
        }
        mx0 = fmaxf(mx0, __shfl_xor_sync(0xffffffffu, mx0, 1));
        mx0 = fmaxf(mx0, __shfl_xor_sync(0xffffffffu, mx0, 2));
        mx1 = fmaxf(mx1, __shfl_xor_sync(0xffffffffu, mx1, 1));
        mx1 = fmaxf(mx1, __shfl_xor_sync(0xffffffffu, mx1, 2));
        float mn0 = fmaxf(m0, mx0), mn1 = fmaxf(m1, mx1);
        float al0 = __expf(m0 - mn0), al1 = __expf(m1 - mn1);
        float ls0 = 0.f, ls1 = 0.f;
        #pragma unroll
        for (int u = 0; u < 8; u++) {
            sacc[u][0] = __expf(sacc[u][0] - mn0);
            sacc[u][1] = __expf(sacc[u][1] - mn0);
            sacc[u][2] = __expf(sacc[u][2] - mn1);
            sacc[u][3] = __expf(sacc[u][3] - mn1);
            ls0 += sacc[u][0] + sacc[u][1];
            ls1 += sacc[u][2] + sacc[u][3];
        }
        ls0 += __shfl_xor_sync(0xffffffffu, ls0, 1);
        ls0 += __shfl_xor_sync(0xffffffffu, ls0, 2);
        ls1 += __shfl_xor_sync(0xffffffffu, ls1, 1);
        ls1 += __shfl_xor_sync(0xffffffffu, ls1, 2);
        l0 = l0*al0 + ls0;  m0 = mn0;
        l1 = l1*al1 + ls1;  m1 = mn1;
        #pragma unroll
        for (int u = 0; u < 8; u++) {
            oacc[u][0] *= al0; oacc[u][1] *= al0;
            oacc[u][2] *= al1; oacc[u][3] *= al1;
        }

        // ---- O += P V (register identity) ----
        #pragma unroll
        for (int j = 0; j < 4; j++) {
            uint32_t a[4];
            a[0] = pack_h2(sacc[2*j][0],   sacc[2*j][1]);
            a[1] = pack_h2(sacc[2*j][2],   sacc[2*j][3]);
            a[2] = pack_h2(sacc[2*j+1][0], sacc[2*j+1][1]);
            a[3] = pack_h2(sacc[2*j+1][2], sacc[2*j+1][3]);
            uint32_t vf[4][4];
            #pragma unroll
            for (int nb = 0; nb < 4; nb++) {
                int row = j*16 + vrow_off;
                int c = nb*2 + vd_sub;
                ldmx4t(vf[nb], (char*)sV[p] + row*128 + ((c ^ (row & 7)) * 16));
            }
            #pragma unroll
            for (int nb = 0; nb < 4; nb++) {
                mmaf16(oacc[2*nb],   a, vf[nb][0], vf[nb][1]);
                mmaf16(oacc[2*nb+1], a, vf[nb][2], vf[nb][3]);
            }
        }

        // refill this buffer with tile t+2; wait for tile t+1
        __syncthreads();
        int nt_ = (t + 2 < NT) ? (t + 2) * 64 : (NT - 1) * 64;
        issueKV(nt_, p);
        CP_COMMIT();
        cp_wait<1>();
        __syncthreads();
    }

    // ---- normalize + bf16 hi/lo split epilogue ----
    const float inv0 = 1.0f / l0, inv1 = 1.0f / l1;
    const int r = q0 + wid*16 + (lane >> 2);
    const size_t base0 = (size_t)(b*SEQL + r) * DIMC + h*HDIM + (lane & 3)*2;
    const size_t base1 = base0 + (size_t)8 * DIMC;
    #pragma unroll
    for (int t = 0; t < 8; t++) {
        float o0 = oacc[t][0]*inv0, o1 = oacc[t][1]*inv0;
        float o2 = oacc[t][2]*inv1, o3 = oacc[t][3]*inv1;
        __nv_bfloat16 h0 = __float2bfloat16(o0), h1 = __float2bfloat16(o1);
        __nv_bfloat16 h2 = __float2bfloat16(o2), h3 = __float2bfloat16(o3);
        __nv_bfloat162 hv, lv;
        hv.x = h0; hv.y = h1;
        lv.x = __float2bfloat16(o0 - __bfloat162float(h0));
        lv.y = __float2bfloat16(o1 - __bfloat162float(h1));
        *(__nv_bfloat162*)(g_aoh + base0 + t*8) = hv;
        *(__nv_bfloat162*)(g_aol + base0 + t*8) = lv;
        hv.x = h2; hv.y = h3;
        lv.x = __float2bfloat16(o2 - __bfloat162float(h2));
        lv.y = __float2bfloat16(o3 - __bfloat162float(h3));
        *(__nv_bfloat162*)(g_aoh + base1 + t*8) = hv;
        *(__nv_bfloat162*)(g_aol + base1 + t*8) = lv;
    }
}

extern "C" void kernel_launch(void* const* d_in, const int* in_sizes, int n_in,
                              void* d_out, int out_size)
{
    const float* x   = (const float*)d_in[0];
    const float* ctx = (const float*)d_in[1];
    const float* Wq  = (const float*)d_in[2];
    const float* bq  = (const float*)d_in[3];
    const float* Wk  = (const float*)d_in[4];
    const float* bk  = (const float*)d_in[5];
    const float* Wv  = (const float*)d_in[6];
    const float* bv  = (const float*)d_in[7];
    const float* Wo  = (const float*)d_in[8];
    const float* bo  = (const float*)d_in[9];
    float* out = (float*)d_out;

    cudaFuncSetAttribute(gemm_tc2,
        cudaFuncAttributeMaxDynamicSharedMemorySize, 2 * STG);

    const int nA4 = NROWS * DIMC / 4;   // 2M float4
    const int nW4 = DIMC * DIMC / 4;    // 256K float4
    split_k<<<nA4 / 256, 256>>>(x,   0, nA4);
    split_k<<<nA4 / 256, 256>>>(ctx, 1, nA4);
    split_k<<<nW4 / 256, 256>>>(Wq,  2, nW4);
    split_k<<<nW4 / 256, 256>>>(Wk,  3, nW4);
    split_k<<<nW4 / 256, 256>>>(Wv,  4, nW4);
    split_k<<<nW4 / 256, 256>>>(Wo,  5, nW4);

    dim3 gg(DIMC / TBN, NROWS / TBM);   // (8, 64)
    gemm_tc2<<<gg, 512, 2*STG>>>(bq, nullptr, 0, 0, 0, 0.125f);  // Q (pre-scaled)
    gemm_tc2<<<gg, 512, 2*STG>>>(bk, nullptr, 1, 1, 1, 1.0f);    // K
    gemm_tc2<<<gg, 512, 2*STG>>>(bv, nullptr, 1, 2, 2, 1.0f);    // V
    attn_tc<<<dim3(SEQL/128, NHEADS, BATCH), 256>>>();           // attention
    gemm_tc2<<<gg, 512, 2*STG>>>(bo, out, 2, 3, 3, 1.0f);        // O proj
}